// round 2
// baseline (speedup 1.0000x reference)
#include <cuda_runtime.h>
#include <cuda_bf16.h>

#define N 512
#define D 128
#define MARGIN 1.0f
#define EPSF 1e-8f

__device__ double g_sum;
__device__ unsigned long long g_cnt;

__global__ void zero_k() {
    g_sum = 0.0;
    g_cnt = 0ULL;
}

__global__ __launch_bounds__(256) void triplet_k(const float* __restrict__ E,
                                                 const int* __restrict__ lab) {
    __shared__ float s_ei[D];
    __shared__ float s_row[N];
    __shared__ int   s_lab[N];
    __shared__ int   s_pos[N];
    __shared__ int   s_np;
    __shared__ double       s_wsum[8];
    __shared__ unsigned int s_wcnt[8];

    const int i   = blockIdx.x;
    const int tid = threadIdx.x;

    if (tid == 0) s_np = 0;
    if (tid < D) s_ei[tid] = E[i * D + tid];
    for (int j = tid; j < N; j += 256) s_lab[j] = lab[j];
    __syncthreads();

    const int labi = s_lab[i];
    const float4* ei4 = (const float4*)s_ei;

    // dm[i, j] for all j; also gather positive indices
    for (int j = tid; j < N; j += 256) {
        const float4* ej = (const float4*)(E + j * D);
        float acc = 0.f;
#pragma unroll
        for (int q = 0; q < D / 4; q++) {
            float4 a = ei4[q];
            float4 b = ej[q];
            acc = fmaf(a.x, b.x, acc);
            acc = fmaf(a.y, b.y, acc);
            acc = fmaf(a.z, b.z, acc);
            acc = fmaf(a.w, b.w, acc);
        }
        s_row[j] = acc;
        if (j != i && s_lab[j] == labi) {
            int p = atomicAdd(&s_np, 1);
            s_pos[p] = j;
        }
    }
    __syncthreads();

    const int np = s_np;
    float lsum = 0.f;
    unsigned int lcnt = 0;

    // hinge over (positive p, candidate k) pairs; negatives filtered by label
    const int total = np * N;
    for (int idx = tid; idx < total; idx += 256) {
        const int p = idx >> 9;        // N == 512
        const int k = idx & (N - 1);
        if (s_lab[k] != labi) {
            const float v = s_row[s_pos[p]] - s_row[k] + MARGIN;
            if (v > 0.f)   lsum += v;
            if (v > EPSF)  lcnt++;
        }
    }

    // block reduction (double for the sum)
    double dsum = (double)lsum;
#pragma unroll
    for (int o = 16; o > 0; o >>= 1) {
        dsum += __shfl_down_sync(0xffffffffu, dsum, o);
        lcnt += __shfl_down_sync(0xffffffffu, lcnt, o);
    }
    const int w = tid >> 5, l = tid & 31;
    if (l == 0) { s_wsum[w] = dsum; s_wcnt[w] = lcnt; }
    __syncthreads();
    if (tid == 0) {
        double t = 0.0;
        unsigned int c = 0;
#pragma unroll
        for (int ww = 0; ww < 8; ww++) { t += s_wsum[ww]; c += s_wcnt[ww]; }
        if (t != 0.0 || c != 0) {
            atomicAdd(&g_sum, t);
            atomicAdd(&g_cnt, (unsigned long long)c);
        }
    }
}

__global__ void fin_k(float* __restrict__ out) {
    out[0] = (float)(g_sum / ((double)g_cnt + (double)EPSF));
}

extern "C" void kernel_launch(void* const* d_in, const int* in_sizes, int n_in,
                              void* d_out, int out_size) {
    const float* E   = (const float*)d_in[0];
    const int*   lab = (const int*)d_in[1];
    float*       out = (float*)d_out;

    zero_k<<<1, 1>>>();
    triplet_k<<<N, 256>>>(E, lab);
    fin_k<<<1, 1>>>(out);
}

// round 3
// speedup vs baseline: 1.5463x; 1.5463x over previous
#include <cuda_runtime.h>
#include <cuda_bf16.h>

#define N 512
#define D 128
#define A 4            // anchors per block
#define T 256          // threads per block
#define NPOS_MAX 64    // max positives per class (512 samples / 64 classes, P(>40) ~ 0)
#define MARGIN 1.0f
#define EPSF 1e-8f

__device__ double             g_sum;
__device__ unsigned long long g_cnt;
__device__ unsigned int       g_done;

__global__ __launch_bounds__(T) void triplet_k(const float* __restrict__ E,
                                               const int* __restrict__ lab,
                                               float* __restrict__ out) {
    __shared__ float        s_ea[A * D];        // 4 anchor vectors (contiguous rows)
    __shared__ float        s_row[A][N];        // dm rows for the 4 anchors
    __shared__ int          s_lab[N];
    __shared__ short        s_pos[A][NPOS_MAX];
    __shared__ int          s_np[A];
    __shared__ double       s_wsum[T / 32];
    __shared__ unsigned int s_wcnt[T / 32];
    __shared__ int          s_last;

    const int i0  = blockIdx.x * A;
    const int tid = threadIdx.x;

    if (tid < A) s_np[tid] = 0;
    // anchors are 4 contiguous rows of E -> linear cooperative copy
    for (int idx = tid; idx < A * D; idx += T) s_ea[idx] = E[i0 * D + idx];
    for (int j = tid; j < N; j += T)           s_lab[j]  = lab[j];
    __syncthreads();

    const float4* ea4 = (const float4*)s_ea;

    // ---- dot phase: each thread owns j and j+256; 4 anchor dots per E-row load ----
    for (int j = tid; j < N; j += T) {
        const float4* ej = (const float4*)(E + j * D);
        float acc0 = 0.f, acc1 = 0.f, acc2 = 0.f, acc3 = 0.f;
#pragma unroll
        for (int q = 0; q < D / 4; q++) {
            const float4 b  = ej[q];
            const float4 a0 = ea4[0 * (D / 4) + q];
            const float4 a1 = ea4[1 * (D / 4) + q];
            const float4 a2 = ea4[2 * (D / 4) + q];
            const float4 a3 = ea4[3 * (D / 4) + q];
            acc0 = fmaf(a0.x, b.x, acc0); acc0 = fmaf(a0.y, b.y, acc0);
            acc0 = fmaf(a0.z, b.z, acc0); acc0 = fmaf(a0.w, b.w, acc0);
            acc1 = fmaf(a1.x, b.x, acc1); acc1 = fmaf(a1.y, b.y, acc1);
            acc1 = fmaf(a1.z, b.z, acc1); acc1 = fmaf(a1.w, b.w, acc1);
            acc2 = fmaf(a2.x, b.x, acc2); acc2 = fmaf(a2.y, b.y, acc2);
            acc2 = fmaf(a2.z, b.z, acc2); acc2 = fmaf(a2.w, b.w, acc2);
            acc3 = fmaf(a3.x, b.x, acc3); acc3 = fmaf(a3.y, b.y, acc3);
            acc3 = fmaf(a3.z, b.z, acc3); acc3 = fmaf(a3.w, b.w, acc3);
        }
        s_row[0][j] = acc0; s_row[1][j] = acc1;
        s_row[2][j] = acc2; s_row[3][j] = acc3;

        const int lj = s_lab[j];
#pragma unroll
        for (int a = 0; a < A; a++) {
            if (j != i0 + a && lj == s_lab[i0 + a]) {
                int p = atomicAdd(&s_np[a], 1);
                s_pos[a][p] = (short)j;
            }
        }
    }
    __syncthreads();

    // ---- hinge phase ----
    float lsum = 0.f;
    unsigned int lcnt = 0;
#pragma unroll
    for (int a = 0; a < A; a++) {
        const int labi  = s_lab[i0 + a];
        const int total = s_np[a] << 9;           // np * N
        for (int idx = tid; idx < total; idx += T) {
            const int p = idx >> 9;
            const int k = idx & (N - 1);
            if (s_lab[k] != labi) {
                const float v = s_row[a][s_pos[a][p]] - s_row[a][k] + MARGIN;
                if (v > 0.f)  lsum += v;
                if (v > EPSF) lcnt++;
            }
        }
    }

    // ---- block reduction ----
    double dsum = (double)lsum;
#pragma unroll
    for (int o = 16; o > 0; o >>= 1) {
        dsum += __shfl_down_sync(0xffffffffu, dsum, o);
        lcnt += __shfl_down_sync(0xffffffffu, lcnt, o);
    }
    const int w = tid >> 5, l = tid & 31;
    if (l == 0) { s_wsum[w] = dsum; s_wcnt[w] = lcnt; }
    __syncthreads();

    if (tid == 0) {
        double t = 0.0;
        unsigned int c = 0;
#pragma unroll
        for (int ww = 0; ww < T / 32; ww++) { t += s_wsum[ww]; c += s_wcnt[ww]; }
        if (t != 0.0 || c != 0) {
            atomicAdd(&g_sum, t);
            atomicAdd(&g_cnt, (unsigned long long)c);
        }
        __threadfence();
        const unsigned int d = atomicAdd(&g_done, 1u);
        s_last = (d == gridDim.x - 1);
    }
    __syncthreads();

    // ---- last block finalizes and resets globals (graph-replay safe) ----
    if (s_last && tid == 0) {
        const double            s  = atomicAdd(&g_sum, 0.0);
        const unsigned long long c = atomicAdd(&g_cnt, 0ULL);
        out[0] = (float)(s / ((double)c + (double)EPSF));
        g_sum  = 0.0;
        g_cnt  = 0ULL;
        atomicExch(&g_done, 0u);
    }
}

extern "C" void kernel_launch(void* const* d_in, const int* in_sizes, int n_in,
                              void* d_out, int out_size) {
    const float* E   = (const float*)d_in[0];
    const int*   lab = (const int*)d_in[1];
    float*       out = (float*)d_out;

    triplet_k<<<N / A, T>>>(E, lab, out);
}

// round 4
// speedup vs baseline: 2.3431x; 1.5153x over previous
#include <cuda_runtime.h>
#include <cuda_bf16.h>

#define N 512
#define D 128
#define A 4            // anchors per block
#define T 512          // threads per block (16 warps -> latency hiding)
#define NPOS_MAX 64
#define MARGIN 1.0f
#define EPSF 1e-8f

__device__ double             g_sum;
__device__ unsigned long long g_cnt;
__device__ unsigned int       g_done;

__global__ __launch_bounds__(T, 1) void triplet_k(const float* __restrict__ E,
                                                  const int* __restrict__ lab,
                                                  float* __restrict__ out) {
    __shared__ float        s_ea[A * D];        // 4 anchor vectors
    __shared__ float        s_row[A][N];        // dm rows for the 4 anchors
    __shared__ int          s_lab[N];
    __shared__ short        s_pos[A][NPOS_MAX];
    __shared__ int          s_np[A];
    __shared__ double       s_wsum[T / 32];
    __shared__ unsigned int s_wcnt[T / 32];
    __shared__ int          s_last;

    const int i0  = blockIdx.x * A;
    const int tid = threadIdx.x;

    if (tid < A) s_np[tid] = 0;
    for (int idx = tid; idx < A * D; idx += T) s_ea[idx] = E[i0 * D + idx];
    for (int j = tid; j < N; j += T)           s_lab[j]  = lab[j];
    __syncthreads();

    const float4* ea4 = (const float4*)s_ea;

    // ---- dot phase: thread tid owns column j = tid (one j per thread) ----
    {
        const int j = tid;                       // T == N
        const float4* ej = (const float4*)(E + j * D);
        float acc0 = 0.f, acc1 = 0.f, acc2 = 0.f, acc3 = 0.f;
#pragma unroll 8
        for (int q = 0; q < D / 4; q++) {
            const float4 b  = ej[q];
            const float4 a0 = ea4[0 * (D / 4) + q];
            const float4 a1 = ea4[1 * (D / 4) + q];
            const float4 a2 = ea4[2 * (D / 4) + q];
            const float4 a3 = ea4[3 * (D / 4) + q];
            acc0 = fmaf(a0.x, b.x, acc0); acc0 = fmaf(a0.y, b.y, acc0);
            acc0 = fmaf(a0.z, b.z, acc0); acc0 = fmaf(a0.w, b.w, acc0);
            acc1 = fmaf(a1.x, b.x, acc1); acc1 = fmaf(a1.y, b.y, acc1);
            acc1 = fmaf(a1.z, b.z, acc1); acc1 = fmaf(a1.w, b.w, acc1);
            acc2 = fmaf(a2.x, b.x, acc2); acc2 = fmaf(a2.y, b.y, acc2);
            acc2 = fmaf(a2.z, b.z, acc2); acc2 = fmaf(a2.w, b.w, acc2);
            acc3 = fmaf(a3.x, b.x, acc3); acc3 = fmaf(a3.y, b.y, acc3);
            acc3 = fmaf(a3.z, b.z, acc3); acc3 = fmaf(a3.w, b.w, acc3);
        }
        s_row[0][j] = acc0; s_row[1][j] = acc1;
        s_row[2][j] = acc2; s_row[3][j] = acc3;

        const int lj = s_lab[j];
#pragma unroll
        for (int a = 0; a < A; a++) {
            if (j != i0 + a && lj == s_lab[i0 + a]) {
                int p = atomicAdd(&s_np[a], 1);
                s_pos[a][p] = (short)j;
            }
        }
    }
    __syncthreads();

    // ---- hinge phase ----
    float lsum = 0.f;
    unsigned int lcnt = 0;
#pragma unroll
    for (int a = 0; a < A; a++) {
        const int labi  = s_lab[i0 + a];
        const int total = s_np[a] << 9;           // np * N
        for (int idx = tid; idx < total; idx += T) {
            const int p = idx >> 9;
            const int k = idx & (N - 1);
            if (s_lab[k] != labi) {
                const float v = s_row[a][s_pos[a][p]] - s_row[a][k] + MARGIN;
                if (v > 0.f)  lsum += v;
                if (v > EPSF) lcnt++;
            }
        }
    }

    // ---- block reduction ----
    double dsum = (double)lsum;
#pragma unroll
    for (int o = 16; o > 0; o >>= 1) {
        dsum += __shfl_down_sync(0xffffffffu, dsum, o);
        lcnt += __shfl_down_sync(0xffffffffu, lcnt, o);
    }
    const int w = tid >> 5, l = tid & 31;
    if (l == 0) { s_wsum[w] = dsum; s_wcnt[w] = lcnt; }
    __syncthreads();

    if (tid == 0) {
        double t = 0.0;
        unsigned int c = 0;
#pragma unroll
        for (int ww = 0; ww < T / 32; ww++) { t += s_wsum[ww]; c += s_wcnt[ww]; }
        if (t != 0.0 || c != 0) {
            atomicAdd(&g_sum, t);
            atomicAdd(&g_cnt, (unsigned long long)c);
        }
        __threadfence();
        const unsigned int d = atomicAdd(&g_done, 1u);
        s_last = (d == gridDim.x - 1);
    }
    __syncthreads();

    // ---- last block finalizes and resets globals (graph-replay safe) ----
    if (s_last && tid == 0) {
        const double             s = atomicAdd(&g_sum, 0.0);
        const unsigned long long c = atomicAdd(&g_cnt, 0ULL);
        out[0] = (float)(s / ((double)c + (double)EPSF));
        g_sum  = 0.0;
        g_cnt  = 0ULL;
        atomicExch(&g_done, 0u);
    }
}

extern "C" void kernel_launch(void* const* d_in, const int* in_sizes, int n_in,
                              void* d_out, int out_size) {
    const float* E   = (const float*)d_in[0];
    const int*   lab = (const int*)d_in[1];
    float*       out = (float*)d_out;

    triplet_k<<<N / A, T>>>(E, lab, out);
}